// round 1
// baseline (speedup 1.0000x reference)
#include <cuda_runtime.h>
#include <cuda_bf16.h>
#include <cstdint>

#define IN_F     4096
#define OUT_F    4096
#define N_TOK    8192
#define GROUP    128
#define NGROUPS  (IN_F / GROUP)     // 32
#define N_STAGES 4
#define QMAXF    15.0f

// Scratch for the dequantized, back-rotated weight [OUT_F, IN_F] (row-major, K contiguous)
__device__ float g_wback[(size_t)OUT_F * IN_F];

// ---------------------------------------------------------------------------
// Kernel 1: per-output-row weight transform.
// One block (128 threads) per weight row. Row lives in shared memory.
// ---------------------------------------------------------------------------
__global__ __launch_bounds__(128) void transform_kernel(
    const float* __restrict__ weight,          // [OUT_F, IN_F]
    const float* __restrict__ channel_scales,  // [IN_F]
    const float* __restrict__ theta,           // [N_STAGES, IN_F/2]
    const float* __restrict__ q_scale,         // [OUT_F*NGROUPS]
    const float* __restrict__ q_zp,            // [OUT_F*NGROUPS]
    const int*   __restrict__ pairs)           // [N_STAGES, IN_F] (local idx within group)
{
    __shared__ float w[IN_F];
    const int row = blockIdx.x;
    const int tid = threadIdx.x;

    const float* wrow = weight + (size_t)row * IN_F;

    // Load + channel scale (vectorized)
    for (int k = tid * 4; k < IN_F; k += 128 * 4) {
        float4 v = *reinterpret_cast<const float4*>(wrow + k);
        float4 c = *reinterpret_cast<const float4*>(channel_scales + k);
        v.x *= c.x; v.y *= c.y; v.z *= c.z; v.w *= c.w;
        *reinterpret_cast<float4*>(&w[k]) = v;
    }
    __syncthreads();

    // Forward rotation stages. Pairs within a stage are disjoint -> no
    // intra-stage hazard; sync between stages.
    for (int r = 0; r < N_STAGES; r++) {
        const int* pr = pairs + r * IN_F;
        const float* tr = theta + r * (IN_F / 2);
        for (int p = tid; p < IN_F / 2; p += 128) {
            int g    = p >> 6;        // group index (64 pairs per group)
            int pp   = p & 63;        // pair within group
            int base = g * GROUP;
            int i = base + pr[base + 2 * pp];
            int j = base + pr[base + 2 * pp + 1];
            float th = tr[g * 64 + pp];
            float s, c;
            sincosf(th, &s, &c);
            float xi = w[i], xj = w[j];
            w[i] =  xi * c + xj * s;
            w[j] = -xi * s + xj * c;
        }
        __syncthreads();
    }

    // Affine 4-bit quant-dequant per group of 128 (round-half-even = rintf,
    // matching jnp.round)
    for (int k = tid; k < IN_F; k += 128) {
        int gi = row * NGROUPS + (k >> 7);
        float s   = fminf(fmaxf(q_scale[gi], 1e-5f), 1e5f);
        float rzp = fminf(fmaxf(-rintf(q_zp[gi]), 0.0f), QMAXF);
        float q   = rintf(w[k] / s) + rzp;
        q = fminf(fmaxf(q, 0.0f), QMAXF);
        w[k] = (q - rzp) * s;
    }
    __syncthreads();

    // Inverse rotation stages: reverse order, negated theta
    // (cos same, sin negated).
    for (int r = N_STAGES - 1; r >= 0; r--) {
        const int* pr = pairs + r * IN_F;
        const float* tr = theta + r * (IN_F / 2);
        for (int p = tid; p < IN_F / 2; p += 128) {
            int g    = p >> 6;
            int pp   = p & 63;
            int base = g * GROUP;
            int i = base + pr[base + 2 * pp];
            int j = base + pr[base + 2 * pp + 1];
            float th = tr[g * 64 + pp];
            float s, c;
            sincosf(th, &s, &c);
            float xi = w[i], xj = w[j];
            w[i] = xi * c - xj * s;
            w[j] = xi * s + xj * c;
        }
        __syncthreads();
    }

    // Unscale + store
    float* orow = g_wback + (size_t)row * IN_F;
    for (int k = tid; k < IN_F; k += 128) {
        orow[k] = w[k] / channel_scales[k];
    }
}

// ---------------------------------------------------------------------------
// Kernel 2: fp32 SIMT GEMM  out[M,N] = x[M,K] . wback[N,K]^T + bias[N]
// 128x128 block tile, BK=8, 256 threads, 8x8 register micro-tile.
// ---------------------------------------------------------------------------
#define BM 128
#define BN 128
#define BK 8
#define TM 8
#define TN 8

__global__ __launch_bounds__(256) void gemm_kernel(
    const float* __restrict__ A,     // x [M, K]
    const float* __restrict__ bias,  // [N]
    float* __restrict__ C)           // [M, N]
{
    const float* B = g_wback;        // [N, K]
    const int K = IN_F;
    const int N = OUT_F;

    __shared__ float As[BK][BM];
    __shared__ float Bs[BK][BN];

    const int bx = blockIdx.x;   // N tile
    const int by = blockIdx.y;   // M tile
    const int tid = threadIdx.x;

    // global->shared load mapping: 2 float4 per K-row; 256 threads cover
    // 128 rows x 2 vectors for both A and B tiles.
    const int loadRow = tid >> 1;          // 0..127
    const int loadCol = (tid & 1) * 4;     // 0 or 4

    // compute mapping: 16x16 thread grid, each thread 8x8 outputs
    const int tx = tid & 15;
    const int ty = tid >> 4;

    const float* Aptr = A + ((size_t)(by * BM + loadRow)) * K + loadCol;
    const float* Bptr = B + ((size_t)(bx * BN + loadRow)) * K + loadCol;

    float acc[TM][TN];
    #pragma unroll
    for (int i = 0; i < TM; i++)
        #pragma unroll
        for (int j = 0; j < TN; j++)
            acc[i][j] = 0.0f;

    for (int k0 = 0; k0 < K; k0 += BK) {
        float4 a = *reinterpret_cast<const float4*>(Aptr + k0);
        float4 b = *reinterpret_cast<const float4*>(Bptr + k0);
        As[loadCol + 0][loadRow] = a.x;
        As[loadCol + 1][loadRow] = a.y;
        As[loadCol + 2][loadRow] = a.z;
        As[loadCol + 3][loadRow] = a.w;
        Bs[loadCol + 0][loadRow] = b.x;
        Bs[loadCol + 1][loadRow] = b.y;
        Bs[loadCol + 2][loadRow] = b.z;
        Bs[loadCol + 3][loadRow] = b.w;
        __syncthreads();

        #pragma unroll
        for (int kk = 0; kk < BK; kk++) {
            float4 a0 = *reinterpret_cast<const float4*>(&As[kk][ty * TM]);
            float4 a1 = *reinterpret_cast<const float4*>(&As[kk][ty * TM + 4]);
            float4 b0 = *reinterpret_cast<const float4*>(&Bs[kk][tx * TN]);
            float4 b1 = *reinterpret_cast<const float4*>(&Bs[kk][tx * TN + 4]);
            float ar[TM] = {a0.x, a0.y, a0.z, a0.w, a1.x, a1.y, a1.z, a1.w};
            float br[TN] = {b0.x, b0.y, b0.z, b0.w, b1.x, b1.y, b1.z, b1.w};
            #pragma unroll
            for (int i = 0; i < TM; i++)
                #pragma unroll
                for (int j = 0; j < TN; j++)
                    acc[i][j] = fmaf(ar[i], br[j], acc[i][j]);
        }
        __syncthreads();
    }

    // epilogue: add bias, vectorized stores
    #pragma unroll
    for (int i = 0; i < TM; i++) {
        const int m = by * BM + ty * TM + i;
        #pragma unroll
        for (int j = 0; j < TN; j += 4) {
            const int n = bx * BN + tx * TN + j;
            float4 o;
            o.x = acc[i][j + 0] + bias[n + 0];
            o.y = acc[i][j + 1] + bias[n + 1];
            o.z = acc[i][j + 2] + bias[n + 2];
            o.w = acc[i][j + 3] + bias[n + 3];
            *reinterpret_cast<float4*>(C + (size_t)m * N + n) = o;
        }
    }
}

// ---------------------------------------------------------------------------
// Launch
// ---------------------------------------------------------------------------
extern "C" void kernel_launch(void* const* d_in, const int* in_sizes, int n_in,
                              void* d_out, int out_size)
{
    const float* x              = (const float*)d_in[0];
    const float* weight         = (const float*)d_in[1];
    const float* bias           = (const float*)d_in[2];
    const float* channel_scales = (const float*)d_in[3];
    const float* theta          = (const float*)d_in[4];
    const float* q_scale        = (const float*)d_in[5];
    const float* q_zp           = (const float*)d_in[6];
    const int*   pairs          = (const int*)d_in[7];
    // d_in[8] = theta_mask (unused by the reference math)
    float* out = (float*)d_out;

    transform_kernel<<<OUT_F, 128>>>(weight, channel_scales, theta,
                                     q_scale, q_zp, pairs);

    dim3 grid(OUT_F / BN, N_TOK / BM);
    gemm_kernel<<<grid, 256>>>(x, bias, out);
}

// round 3
// speedup vs baseline: 3.0497x; 3.0497x over previous
#include <cuda_runtime.h>
#include <cuda_bf16.h>
#include <cstdint>

#define IN_F     4096
#define OUT_F    4096
#define N_TOK    8192
#define GROUP    128
#define NGROUPS  (IN_F / GROUP)
#define N_STAGES 4
#define QMAXF    15.0f

// ---------------- scratch (device globals; no runtime allocation) ----------
__device__ __nv_bfloat16 g_w_hi[(size_t)OUT_F * IN_F];
__device__ __nv_bfloat16 g_w_lo[(size_t)OUT_F * IN_F];
__device__ __nv_bfloat16 g_x_hi[(size_t)N_TOK * IN_F];
__device__ __nv_bfloat16 g_x_lo[(size_t)N_TOK * IN_F];

// ---------------------------------------------------------------------------
// Kernel 0: split x into bf16 hi/lo
// ---------------------------------------------------------------------------
__global__ __launch_bounds__(256) void convert_x_kernel(const float* __restrict__ x)
{
    size_t i = ((size_t)blockIdx.x * 256 + threadIdx.x) * 4;
    float4 v = *reinterpret_cast<const float4*>(x + i);
    __nv_bfloat16 h0 = __float2bfloat16(v.x);
    __nv_bfloat16 h1 = __float2bfloat16(v.y);
    __nv_bfloat16 h2 = __float2bfloat16(v.z);
    __nv_bfloat16 h3 = __float2bfloat16(v.w);
    __nv_bfloat16 l0 = __float2bfloat16(v.x - __bfloat162float(h0));
    __nv_bfloat16 l1 = __float2bfloat16(v.y - __bfloat162float(h1));
    __nv_bfloat16 l2 = __float2bfloat16(v.z - __bfloat162float(h2));
    __nv_bfloat16 l3 = __float2bfloat16(v.w - __bfloat162float(h3));
    *reinterpret_cast<__nv_bfloat162*>(g_x_hi + i)     = __nv_bfloat162(h0, h1);
    *reinterpret_cast<__nv_bfloat162*>(g_x_hi + i + 2) = __nv_bfloat162(h2, h3);
    *reinterpret_cast<__nv_bfloat162*>(g_x_lo + i)     = __nv_bfloat162(l0, l1);
    *reinterpret_cast<__nv_bfloat162*>(g_x_lo + i + 2) = __nv_bfloat162(l2, l3);
}

// ---------------------------------------------------------------------------
// Kernel 1: weight transform -> w_back, split into bf16 hi/lo
// ---------------------------------------------------------------------------
__global__ __launch_bounds__(128) void transform_kernel(
    const float* __restrict__ weight,
    const float* __restrict__ channel_scales,
    const float* __restrict__ theta,
    const float* __restrict__ q_scale,
    const float* __restrict__ q_zp,
    const int*   __restrict__ pairs)
{
    __shared__ float w[IN_F];
    const int row = blockIdx.x;
    const int tid = threadIdx.x;
    const float* wrow = weight + (size_t)row * IN_F;

    for (int k = tid * 4; k < IN_F; k += 128 * 4) {
        float4 v = *reinterpret_cast<const float4*>(wrow + k);
        float4 c = *reinterpret_cast<const float4*>(channel_scales + k);
        v.x *= c.x; v.y *= c.y; v.z *= c.z; v.w *= c.w;
        *reinterpret_cast<float4*>(&w[k]) = v;
    }
    __syncthreads();

    for (int r = 0; r < N_STAGES; r++) {
        const int* pr = pairs + r * IN_F;
        const float* tr = theta + r * (IN_F / 2);
        for (int p = tid; p < IN_F / 2; p += 128) {
            int g = p >> 6, pp = p & 63, base = g * GROUP;
            int i = base + pr[base + 2 * pp];
            int j = base + pr[base + 2 * pp + 1];
            float s, c;
            sincosf(tr[g * 64 + pp], &s, &c);
            float xi = w[i], xj = w[j];
            w[i] =  xi * c + xj * s;
            w[j] = -xi * s + xj * c;
        }
        __syncthreads();
    }

    for (int k = tid; k < IN_F; k += 128) {
        int gi = row * NGROUPS + (k >> 7);
        float s   = fminf(fmaxf(q_scale[gi], 1e-5f), 1e5f);
        float rzp = fminf(fmaxf(-rintf(q_zp[gi]), 0.0f), QMAXF);
        float q   = rintf(w[k] / s) + rzp;
        q = fminf(fmaxf(q, 0.0f), QMAXF);
        w[k] = (q - rzp) * s;
    }
    __syncthreads();

    for (int r = N_STAGES - 1; r >= 0; r--) {
        const int* pr = pairs + r * IN_F;
        const float* tr = theta + r * (IN_F / 2);
        for (int p = tid; p < IN_F / 2; p += 128) {
            int g = p >> 6, pp = p & 63, base = g * GROUP;
            int i = base + pr[base + 2 * pp];
            int j = base + pr[base + 2 * pp + 1];
            float s, c;
            sincosf(tr[g * 64 + pp], &s, &c);
            float xi = w[i], xj = w[j];
            w[i] = xi * c - xj * s;
            w[j] = xi * s + xj * c;
        }
        __syncthreads();
    }

    for (int k = tid; k < IN_F; k += 128) {
        float wb = w[k] / channel_scales[k];
        __nv_bfloat16 h = __float2bfloat16(wb);
        __nv_bfloat16 l = __float2bfloat16(wb - __bfloat162float(h));
        g_w_hi[(size_t)row * IN_F + k] = h;
        g_w_lo[(size_t)row * IN_F + k] = l;
    }
}

// ---------------------------------------------------------------------------
// Kernel 2: mma.sync bf16 split GEMM.
// C[8192,4096] = sum over 3 K-segments of Aseg[8192,4096] . Bseg[4096,4096]^T
//   seg0: x_hi . w_hi,  seg1: x_lo . w_hi,  seg2: x_hi . w_lo   (+ bias)
// CTA tile 128(M) x 256(N), 8 warps (2x4), warp tile 64x64, BK=64,
// 4-stage cp.async pipeline, SW128-swizzled smem, ldmatrix.x4.
// ---------------------------------------------------------------------------
#define BM 128
#define BN 256
#define BK 64
#define KSTAGES 4
#define A_STAGE_BYTES (BM * BK * 2)           // 16384
#define B_STAGE_BYTES (BN * BK * 2)           // 32768
#define STAGE_BYTES   (A_STAGE_BYTES + B_STAGE_BYTES)   // 49152
#define GEMM_SMEM     (KSTAGES * STAGE_BYTES)           // 196608
#define NKT           (3 * IN_F / BK)          // 192 K-chunks total

__device__ __forceinline__ uint32_t smem_u32(const void* p) {
    uint32_t a;
    asm("{ .reg .u64 t; cvta.to.shared.u64 t, %1; cvt.u32.u64 %0, t; }"
        : "=r"(a) : "l"(p));
    return a;
}
__device__ __forceinline__ void cp_async16(uint32_t saddr, const void* gptr) {
    asm volatile("cp.async.cg.shared.global [%0], [%1], 16;"
                 :: "r"(saddr), "l"(gptr));
}
#define CP_COMMIT() asm volatile("cp.async.commit_group;" ::: "memory")
#define CP_WAIT(n)  asm volatile("cp.async.wait_group %0;" :: "n"(n) : "memory")

__device__ __forceinline__ void ldmatrix_x4(uint32_t* r, uint32_t addr) {
    asm volatile("ldmatrix.sync.aligned.m8n8.x4.shared.b16 {%0,%1,%2,%3}, [%4];"
                 : "=r"(r[0]), "=r"(r[1]), "=r"(r[2]), "=r"(r[3]) : "r"(addr));
}
__device__ __forceinline__ void mma16816(float* c, const uint32_t* a,
                                         const uint32_t* b) {
    asm volatile("mma.sync.aligned.m16n8k16.row.col.f32.bf16.bf16.f32 "
                 "{%0,%1,%2,%3}, {%4,%5,%6,%7}, {%8,%9}, {%0,%1,%2,%3};"
                 : "+f"(c[0]), "+f"(c[1]), "+f"(c[2]), "+f"(c[3])
                 : "r"(a[0]), "r"(a[1]), "r"(a[2]), "r"(a[3]),
                   "r"(b[0]), "r"(b[1]));
}

__global__ __launch_bounds__(256, 1) void gemm_mma_kernel(
    const float* __restrict__ bias, float* __restrict__ C)
{
    extern __shared__ char smem[];
    const uint32_t sbase = smem_u32(smem);
    const int tid  = threadIdx.x;
    const int wid  = tid >> 5;
    const int lane = tid & 31;
    const int bn = blockIdx.x;           // 0..15
    const int bm = blockIdx.y;           // 0..63
    const int warp_m = wid >> 2;         // 0..1
    const int warp_n = wid & 3;          // 0..3

    // ---- global source pointers per segment --------------------------------
    const __nv_bfloat16* Aseg[3];
    const __nv_bfloat16* Bseg[3];
    Aseg[0] = g_x_hi + (size_t)(bm * BM) * IN_F;
    Aseg[1] = g_x_lo + (size_t)(bm * BM) * IN_F;
    Aseg[2] = Aseg[0];
    Bseg[0] = g_w_hi + (size_t)(bn * BN) * IN_F;
    Bseg[1] = Bseg[0];
    Bseg[2] = g_w_lo + (size_t)(bn * BN) * IN_F;

    // ---- cp.async mapping (per thread, fixed) ------------------------------
    // A: 1024 16B-chunks (128 rows x 8 chunks), 4 per thread
    // B: 2048 16B-chunks (256 rows x 8 chunks), 8 per thread
    // swizzle: chunk' = chunk ^ (row & 7)
    float acc[4][8][4];
    #pragma unroll
    for (int i = 0; i < 4; i++)
        #pragma unroll
        for (int j = 0; j < 8; j++)
            #pragma unroll
            for (int k = 0; k < 4; k++) acc[i][j][k] = 0.0f;

    auto load_stage = [&](int kt) {
        const int buf = kt & (KSTAGES - 1);
        const int seg = kt / (IN_F / BK);        // 0..2
        const int ko  = (kt % (IN_F / BK)) * BK; // element offset in K
        const __nv_bfloat16* Ag = Aseg[seg] + ko;
        const __nv_bfloat16* Bg = Bseg[seg] + ko;
        const uint32_t sA = sbase + buf * STAGE_BYTES;
        const uint32_t sB = sA + A_STAGE_BYTES;
        #pragma unroll
        for (int t = 0; t < 4; t++) {
            int v = tid + t * 256;
            int r = v >> 3, c = v & 7;
            uint32_t off = (uint32_t)(r << 7) + (uint32_t)((c ^ (r & 7)) << 4);
            cp_async16(sA + off, Ag + (size_t)r * IN_F + c * 8);
        }
        #pragma unroll
        for (int t = 0; t < 8; t++) {
            int v = tid + t * 256;
            int r = v >> 3, c = v & 7;
            uint32_t off = (uint32_t)(r << 7) + (uint32_t)((c ^ (r & 7)) << 4);
            cp_async16(sB + off, Bg + (size_t)r * IN_F + c * 8);
        }
    };

    // ---- ldmatrix per-thread invariants ------------------------------------
    const int m_lane  = warp_m * 64 + (lane & 15);   // A matrix row for this lane
    const int a_half  = lane >> 4;                   // k-chunk half (0/1)
    const int xa      = m_lane & 7;
    const int n_lane  = warp_n * 64 + (lane & 7) + ((lane >> 4) << 3);
    const int b_half  = (lane >> 3) & 1;
    const int xb      = n_lane & 7;

    // ---- prologue -----------------------------------------------------------
    #pragma unroll
    for (int s = 0; s < KSTAGES - 1; s++) {
        load_stage(s);
        CP_COMMIT();
    }

    // ---- mainloop -----------------------------------------------------------
    for (int kt = 0; kt < NKT; kt++) {
        CP_WAIT(KSTAGES - 2);
        __syncthreads();

        if (kt + KSTAGES - 1 < NKT) load_stage(kt + KSTAGES - 1);
        CP_COMMIT();

        const int buf = kt & (KSTAGES - 1);
        const uint32_t sA = sbase + buf * STAGE_BYTES;
        const uint32_t sB = sA + A_STAGE_BYTES;
        const uint32_t aRow = sA + (uint32_t)(m_lane << 7);
        const uint32_t bRow = sB + (uint32_t)(n_lane << 7);

        #pragma unroll
        for (int kk = 0; kk < 4; kk++) {
            uint32_t a_frag[4][4];
            uint32_t b_frag[4][4];
            const uint32_t ac = (uint32_t)(((kk * 2 + a_half) ^ xa) << 4);
            const uint32_t bc = (uint32_t)(((kk * 2 + b_half) ^ xb) << 4);
            #pragma unroll
            for (int mt = 0; mt < 4; mt++)
                ldmatrix_x4(a_frag[mt], aRow + (uint32_t)(mt << 11) + ac);
            #pragma unroll
            for (int nt = 0; nt < 4; nt++)
                ldmatrix_x4(b_frag[nt], bRow + (uint32_t)(nt << 11) + bc);
            #pragma unroll
            for (int mt = 0; mt < 4; mt++) {
                #pragma unroll
                for (int nt = 0; nt < 4; nt++) {
                    mma16816(acc[mt][2 * nt],     a_frag[mt], &b_frag[nt][0]);
                    mma16816(acc[mt][2 * nt + 1], a_frag[mt], &b_frag[nt][2]);
                }
            }
        }
    }

    // ---- epilogue -----------------------------------------------------------
    const int row_base = bm * BM + warp_m * 64 + (lane >> 2);
    const int col_base = bn * BN + warp_n * 64 + 2 * (lane & 3);
    #pragma unroll
    for (int mt = 0; mt < 4; mt++) {
        const int r0 = row_base + mt * 16;
        #pragma unroll
        for (int n8 = 0; n8 < 8; n8++) {
            const int col = col_base + n8 * 8;
            float2 bv = *reinterpret_cast<const float2*>(bias + col);
            float2 o0, o1;
            o0.x = acc[mt][n8][0] + bv.x;
            o0.y = acc[mt][n8][1] + bv.y;
            o1.x = acc[mt][n8][2] + bv.x;
            o1.y = acc[mt][n8][3] + bv.y;
            *reinterpret_cast<float2*>(C + (size_t)r0 * OUT_F + col)       = o0;
            *reinterpret_cast<float2*>(C + (size_t)(r0 + 8) * OUT_F + col) = o1;
        }
    }
}

// ---------------------------------------------------------------------------
// Launch
// ---------------------------------------------------------------------------
extern "C" void kernel_launch(void* const* d_in, const int* in_sizes, int n_in,
                              void* d_out, int out_size)
{
    const float* x              = (const float*)d_in[0];
    const float* weight         = (const float*)d_in[1];
    const float* bias           = (const float*)d_in[2];
    const float* channel_scales = (const float*)d_in[3];
    const float* theta          = (const float*)d_in[4];
    const float* q_scale        = (const float*)d_in[5];
    const float* q_zp           = (const float*)d_in[6];
    const int*   pairs          = (const int*)d_in[7];
    float* out = (float*)d_out;

    cudaFuncSetAttribute(gemm_mma_kernel,
                         cudaFuncAttributeMaxDynamicSharedMemorySize, GEMM_SMEM);

    convert_x_kernel<<<(size_t)N_TOK * IN_F / 4 / 256, 256>>>(x);
    transform_kernel<<<OUT_F, 128>>>(weight, channel_scales, theta,
                                     q_scale, q_zp, pairs);

    dim3 grid(OUT_F / BN, N_TOK / BM);
    gemm_mma_kernel<<<grid, 256, GEMM_SMEM>>>(bias, out);
}

// round 4
// speedup vs baseline: 8.2948x; 2.7199x over previous
#include <cuda_runtime.h>
#include <cuda_fp16.h>
#include <cstdint>

#define IN_F     4096
#define OUT_F    4096
#define N_TOK    8192
#define GROUP    128
#define NGROUPS  (IN_F / GROUP)
#define N_STAGES 4
#define QMAXF    15.0f

// ---------------- scratch (device globals; no runtime allocation) ----------
__device__ __half g_w_h[(size_t)OUT_F * IN_F];
__device__ __half g_x_h[(size_t)N_TOK * IN_F];
__device__ float2 g_cs[N_STAGES * (IN_F / 2)];   // (cos, sin) per stage/pair

// ---------------------------------------------------------------------------
// Kernel -1: precompute cos/sin of theta (tiny)
// ---------------------------------------------------------------------------
__global__ __launch_bounds__(256) void precompute_cs_kernel(const float* __restrict__ theta)
{
    int i = blockIdx.x * 256 + threadIdx.x;          // 8192 total
    float s, c;
    sincosf(theta[i], &s, &c);
    g_cs[i] = make_float2(c, s);
}

// ---------------------------------------------------------------------------
// Kernel 0: x -> fp16
// ---------------------------------------------------------------------------
__global__ __launch_bounds__(256) void convert_x_kernel(const float* __restrict__ x)
{
    size_t i = ((size_t)blockIdx.x * 256 + threadIdx.x) * 4;
    float4 v = *reinterpret_cast<const float4*>(x + i);
    __half2 h0 = __floats2half2_rn(v.x, v.y);
    __half2 h1 = __floats2half2_rn(v.z, v.w);
    *reinterpret_cast<__half2*>(g_x_h + i)     = h0;
    *reinterpret_cast<__half2*>(g_x_h + i + 2) = h1;
}

// ---------------------------------------------------------------------------
// Kernel 1: weight transform. Block = (group g, 64 rows). All tables in smem.
// ---------------------------------------------------------------------------
#define ROWS_PB 64
#define WPAD    132            // row stride in floats (multiple of 4, !=0 mod 32)

__global__ __launch_bounds__(256) void transform_kernel(
    const float* __restrict__ weight,
    const float* __restrict__ channel_scales,
    const float* __restrict__ q_scale,
    const float* __restrict__ q_zp,
    const int*   __restrict__ pairs)
{
    const int g    = blockIdx.x;            // 0..31
    const int row0 = blockIdx.y * ROWS_PB;  // 0..4032
    const int tid  = threadIdx.x;

    __shared__ float w[ROWS_PB][WPAD];
    __shared__ float cs_c[N_STAGES][64], cs_s[N_STAGES][64];
    __shared__ int   pi[N_STAGES][64], pj[N_STAGES][64];
    __shared__ float csc[GROUP];
    __shared__ float qs[ROWS_PB], qz[ROWS_PB];

    // tables
    if (tid < GROUP) csc[tid] = channel_scales[g * GROUP + tid];
    for (int t = tid; t < N_STAGES * 64; t += 256) {
        int st = t >> 6, p = t & 63;
        float2 cs = g_cs[st * (IN_F / 2) + g * 64 + p];
        cs_c[st][p] = cs.x;
        cs_s[st][p] = cs.y;
        pi[st][p] = pairs[st * IN_F + g * GROUP + 2 * p];
        pj[st][p] = pairs[st * IN_F + g * GROUP + 2 * p + 1];
    }
    if (tid < ROWS_PB) {
        int gi = (row0 + tid) * NGROUPS + g;
        qs[tid] = fminf(fmaxf(q_scale[gi], 1e-5f), 1e5f);
        qz[tid] = fminf(fmaxf(-rintf(q_zp[gi]), 0.0f), QMAXF);
    }
    __syncthreads();

    // load w slice, apply channel scale (float4-coalesced)
    for (int idx = tid; idx < ROWS_PB * (GROUP / 4); idx += 256) {
        int r  = idx >> 5;           // /32
        int c4 = (idx & 31) * 4;
        float4 v = *reinterpret_cast<const float4*>(
            weight + (size_t)(row0 + r) * IN_F + g * GROUP + c4);
        v.x *= csc[c4];
        v.y *= csc[c4 + 1];
        v.z *= csc[c4 + 2];
        v.w *= csc[c4 + 3];
        *reinterpret_cast<float4*>(&w[r][c4]) = v;
    }
    __syncthreads();

    // forward rotations
    #pragma unroll
    for (int st = 0; st < N_STAGES; st++) {
        for (int t = tid; t < ROWS_PB * 64; t += 256) {
            int r = t >> 6, p = t & 63;
            float c = cs_c[st][p], s = cs_s[st][p];
            int i = pi[st][p], j = pj[st][p];
            float xi = w[r][i], xj = w[r][j];
            w[r][i] =  xi * c + xj * s;
            w[r][j] = -xi * s + xj * c;
        }
        __syncthreads();
    }

    // quant-dequant
    for (int t = tid; t < ROWS_PB * GROUP; t += 256) {
        int r = t >> 7, c = t & 127;
        float s = qs[r], rzp = qz[r];
        float q = rintf(w[r][c] / s) + rzp;
        q = fminf(fmaxf(q, 0.0f), QMAXF);
        w[r][c] = (q - rzp) * s;
    }
    __syncthreads();

    // inverse rotations
    #pragma unroll
    for (int st = N_STAGES - 1; st >= 0; st--) {
        for (int t = tid; t < ROWS_PB * 64; t += 256) {
            int r = t >> 6, p = t & 63;
            float c = cs_c[st][p], s = cs_s[st][p];
            int i = pi[st][p], j = pj[st][p];
            float xi = w[r][i], xj = w[r][j];
            w[r][i] = xi * c - xj * s;
            w[r][j] = xi * s + xj * c;
        }
        __syncthreads();
    }

    // unscale + fp16 store (half2-coalesced)
    for (int t = tid; t < ROWS_PB * (GROUP / 2); t += 256) {
        int r  = t >> 6;
        int c2 = (t & 63) * 2;
        float a = w[r][c2]     / csc[c2];
        float b = w[r][c2 + 1] / csc[c2 + 1];
        *reinterpret_cast<__half2*>(
            g_w_h + (size_t)(row0 + r) * IN_F + g * GROUP + c2) =
            __floats2half2_rn(a, b);
    }
}

// ---------------------------------------------------------------------------
// Kernel 2: single fp16 mma.sync GEMM.  C = x_h . w_h^T + bias
// CTA tile 128(M) x 256(N), 8 warps (2x4), warp tile 64x64, BK=64,
// 4-stage cp.async pipeline, swizzled smem, ldmatrix.x4. (validated in R3)
// ---------------------------------------------------------------------------
#define BM 128
#define BN 256
#define BK 64
#define KSTAGES 4
#define A_STAGE_BYTES (BM * BK * 2)
#define B_STAGE_BYTES (BN * BK * 2)
#define STAGE_BYTES   (A_STAGE_BYTES + B_STAGE_BYTES)
#define GEMM_SMEM     (KSTAGES * STAGE_BYTES)            // 196608
#define NKT           (IN_F / BK)                        // 64

__device__ __forceinline__ uint32_t smem_u32(const void* p) {
    uint32_t a;
    asm("{ .reg .u64 t; cvta.to.shared.u64 t, %1; cvt.u32.u64 %0, t; }"
        : "=r"(a) : "l"(p));
    return a;
}
__device__ __forceinline__ void cp_async16(uint32_t saddr, const void* gptr) {
    asm volatile("cp.async.cg.shared.global [%0], [%1], 16;"
                 :: "r"(saddr), "l"(gptr));
}
#define CP_COMMIT() asm volatile("cp.async.commit_group;" ::: "memory")
#define CP_WAIT(n)  asm volatile("cp.async.wait_group %0;" :: "n"(n) : "memory")

__device__ __forceinline__ void ldmatrix_x4(uint32_t* r, uint32_t addr) {
    asm volatile("ldmatrix.sync.aligned.m8n8.x4.shared.b16 {%0,%1,%2,%3}, [%4];"
                 : "=r"(r[0]), "=r"(r[1]), "=r"(r[2]), "=r"(r[3]) : "r"(addr));
}
__device__ __forceinline__ void mma16816(float* c, const uint32_t* a,
                                         const uint32_t* b) {
    asm volatile("mma.sync.aligned.m16n8k16.row.col.f32.f16.f16.f32 "
                 "{%0,%1,%2,%3}, {%4,%5,%6,%7}, {%8,%9}, {%0,%1,%2,%3};"
                 : "+f"(c[0]), "+f"(c[1]), "+f"(c[2]), "+f"(c[3])
                 : "r"(a[0]), "r"(a[1]), "r"(a[2]), "r"(a[3]),
                   "r"(b[0]), "r"(b[1]));
}

__global__ __launch_bounds__(256, 1) void gemm_mma_kernel(
    const float* __restrict__ bias, float* __restrict__ C)
{
    extern __shared__ char smem[];
    const uint32_t sbase = smem_u32(smem);
    const int tid  = threadIdx.x;
    const int wid  = tid >> 5;
    const int lane = tid & 31;
    const int bn = blockIdx.x;
    const int bm = blockIdx.y;
    const int warp_m = wid >> 2;
    const int warp_n = wid & 3;

    const __half* Ag0 = g_x_h + (size_t)(bm * BM) * IN_F;
    const __half* Bg0 = g_w_h + (size_t)(bn * BN) * IN_F;

    float acc[4][8][4];
    #pragma unroll
    for (int i = 0; i < 4; i++)
        #pragma unroll
        for (int j = 0; j < 8; j++)
            #pragma unroll
            for (int k = 0; k < 4; k++) acc[i][j][k] = 0.0f;

    auto load_stage = [&](int kt) {
        const int buf = kt & (KSTAGES - 1);
        const int ko  = kt * BK;
        const __half* Ag = Ag0 + ko;
        const __half* Bg = Bg0 + ko;
        const uint32_t sA = sbase + buf * STAGE_BYTES;
        const uint32_t sB = sA + A_STAGE_BYTES;
        #pragma unroll
        for (int t = 0; t < 4; t++) {
            int v = tid + t * 256;
            int r = v >> 3, c = v & 7;
            uint32_t off = (uint32_t)(r << 7) + (uint32_t)((c ^ (r & 7)) << 4);
            cp_async16(sA + off, Ag + (size_t)r * IN_F + c * 8);
        }
        #pragma unroll
        for (int t = 0; t < 8; t++) {
            int v = tid + t * 256;
            int r = v >> 3, c = v & 7;
            uint32_t off = (uint32_t)(r << 7) + (uint32_t)((c ^ (r & 7)) << 4);
            cp_async16(sB + off, Bg + (size_t)r * IN_F + c * 8);
        }
    };

    const int m_lane  = warp_m * 64 + (lane & 15);
    const int a_half  = lane >> 4;
    const int xa      = m_lane & 7;
    const int n_lane  = warp_n * 64 + (lane & 7) + ((lane >> 4) << 3);
    const int b_half  = (lane >> 3) & 1;
    const int xb      = n_lane & 7;

    #pragma unroll
    for (int s = 0; s < KSTAGES - 1; s++) {
        load_stage(s);
        CP_COMMIT();
    }

    for (int kt = 0; kt < NKT; kt++) {
        CP_WAIT(KSTAGES - 2);
        __syncthreads();

        if (kt + KSTAGES - 1 < NKT) load_stage(kt + KSTAGES - 1);
        CP_COMMIT();

        const int buf = kt & (KSTAGES - 1);
        const uint32_t sA = sbase + buf * STAGE_BYTES;
        const uint32_t sB = sA + A_STAGE_BYTES;
        const uint32_t aRow = sA + (uint32_t)(m_lane << 7);
        const uint32_t bRow = sB + (uint32_t)(n_lane << 7);

        #pragma unroll
        for (int kk = 0; kk < 4; kk++) {
            uint32_t a_frag[4][4];
            uint32_t b_frag[4][4];
            const uint32_t ac = (uint32_t)(((kk * 2 + a_half) ^ xa) << 4);
            const uint32_t bc = (uint32_t)(((kk * 2 + b_half) ^ xb) << 4);
            #pragma unroll
            for (int mt = 0; mt < 4; mt++)
                ldmatrix_x4(a_frag[mt], aRow + (uint32_t)(mt << 11) + ac);
            #pragma unroll
            for (int nt = 0; nt < 4; nt++)
                ldmatrix_x4(b_frag[nt], bRow + (uint32_t)(nt << 11) + bc);
            #pragma unroll
            for (int mt = 0; mt < 4; mt++) {
                #pragma unroll
                for (int nt = 0; nt < 4; nt++) {
                    mma16816(acc[mt][2 * nt],     a_frag[mt], &b_frag[nt][0]);
                    mma16816(acc[mt][2 * nt + 1], a_frag[mt], &b_frag[nt][2]);
                }
            }
        }
    }

    const int row_base = bm * BM + warp_m * 64 + (lane >> 2);
    const int col_base = bn * BN + warp_n * 64 + 2 * (lane & 3);
    #pragma unroll
    for (int mt = 0; mt < 4; mt++) {
        const int r0 = row_base + mt * 16;
        #pragma unroll
        for (int n8 = 0; n8 < 8; n8++) {
            const int col = col_base + n8 * 8;
            float2 bv = *reinterpret_cast<const float2*>(bias + col);
            float2 o0, o1;
            o0.x = acc[mt][n8][0] + bv.x;
            o0.y = acc[mt][n8][1] + bv.y;
            o1.x = acc[mt][n8][2] + bv.x;
            o1.y = acc[mt][n8][3] + bv.y;
            *reinterpret_cast<float2*>(C + (size_t)r0 * OUT_F + col)       = o0;
            *reinterpret_cast<float2*>(C + (size_t)(r0 + 8) * OUT_F + col) = o1;
        }
    }
}

// ---------------------------------------------------------------------------
// Launch
// ---------------------------------------------------------------------------
extern "C" void kernel_launch(void* const* d_in, const int* in_sizes, int n_in,
                              void* d_out, int out_size)
{
    const float* x              = (const float*)d_in[0];
    const float* weight         = (const float*)d_in[1];
    const float* bias           = (const float*)d_in[2];
    const float* channel_scales = (const float*)d_in[3];
    const float* theta          = (const float*)d_in[4];
    const float* q_scale        = (const float*)d_in[5];
    const float* q_zp           = (const float*)d_in[6];
    const int*   pairs          = (const int*)d_in[7];
    float* out = (float*)d_out;

    cudaFuncSetAttribute(gemm_mma_kernel,
                         cudaFuncAttributeMaxDynamicSharedMemorySize, GEMM_SMEM);

    precompute_cs_kernel<<<N_STAGES * (IN_F / 2) / 256, 256>>>(theta);
    convert_x_kernel<<<(size_t)N_TOK * IN_F / 4 / 256, 256>>>(x);

    dim3 tgrid(NGROUPS, OUT_F / ROWS_PB);
    transform_kernel<<<tgrid, 256>>>(weight, channel_scales,
                                     q_scale, q_zp, pairs);

    dim3 grid(OUT_F / BN, N_TOK / BM);
    gemm_mma_kernel<<<grid, 256, GEMM_SMEM>>>(bias, out);
}

// round 6
// speedup vs baseline: 8.3596x; 1.0078x over previous
#include <cuda_runtime.h>
#include <cuda_fp16.h>
#include <cstdint>

#define IN_F     4096
#define OUT_F    4096
#define N_TOK    8192
#define GROUP    128
#define NGROUPS  (IN_F / GROUP)
#define N_STAGES 4
#define QMAXF    15.0f

// ---------------- scratch (device globals; no runtime allocation) ----------
__device__ __half g_w_h[(size_t)OUT_F * IN_F];
__device__ __half g_x_h[(size_t)N_TOK * IN_F];

// ---------------------------------------------------------------------------
// Kernel 0: x -> fp16 (8 elems/thread, 16B stores)
// ---------------------------------------------------------------------------
__global__ __launch_bounds__(256) void convert_x_kernel(const float* __restrict__ x)
{
    size_t i = ((size_t)blockIdx.x * 256 + threadIdx.x) * 8;
    float4 v0 = *reinterpret_cast<const float4*>(x + i);
    float4 v1 = *reinterpret_cast<const float4*>(x + i + 4);
    __half2 h[4];
    h[0] = __floats2half2_rn(v0.x, v0.y);
    h[1] = __floats2half2_rn(v0.z, v0.w);
    h[2] = __floats2half2_rn(v1.x, v1.y);
    h[3] = __floats2half2_rn(v1.z, v1.w);
    *reinterpret_cast<uint4*>(g_x_h + i) = *reinterpret_cast<const uint4*>(h);
}

// ---------------------------------------------------------------------------
// Kernel 1: weight transform. Block = (group g, 64 rows). Tables in smem,
// sincos computed in-block (256 angles, 1 per thread).
// ---------------------------------------------------------------------------
#define ROWS_PB 64
#define WPAD    132

__global__ __launch_bounds__(256) void transform_kernel(
    const float* __restrict__ weight,
    const float* __restrict__ channel_scales,
    const float* __restrict__ theta,
    const float* __restrict__ q_scale,
    const float* __restrict__ q_zp,
    const int*   __restrict__ pairs)
{
    const int g    = blockIdx.x;
    const int row0 = blockIdx.y * ROWS_PB;
    const int tid  = threadIdx.x;

    __shared__ float w[ROWS_PB][WPAD];
    __shared__ float cs_c[N_STAGES][64], cs_s[N_STAGES][64];
    __shared__ int   pi[N_STAGES][64], pj[N_STAGES][64];
    __shared__ float csc[GROUP];
    __shared__ float qs[ROWS_PB], qz[ROWS_PB];

    if (tid < GROUP) csc[tid] = channel_scales[g * GROUP + tid];
    {
        int st = tid >> 6, p = tid & 63;   // 256 threads = 4 stages x 64 pairs
        float s, c;
        sincosf(theta[st * (IN_F / 2) + g * 64 + p], &s, &c);
        cs_c[st][p] = c;
        cs_s[st][p] = s;
        pi[st][p] = pairs[st * IN_F + g * GROUP + 2 * p];
        pj[st][p] = pairs[st * IN_F + g * GROUP + 2 * p + 1];
    }
    if (tid < ROWS_PB) {
        int gi = (row0 + tid) * NGROUPS + g;
        qs[tid] = fminf(fmaxf(q_scale[gi], 1e-5f), 1e5f);
        qz[tid] = fminf(fmaxf(-rintf(q_zp[gi]), 0.0f), QMAXF);
    }
    __syncthreads();

    for (int idx = tid; idx < ROWS_PB * (GROUP / 4); idx += 256) {
        int r  = idx >> 5;
        int c4 = (idx & 31) * 4;
        float4 v = *reinterpret_cast<const float4*>(
            weight + (size_t)(row0 + r) * IN_F + g * GROUP + c4);
        v.x *= csc[c4];
        v.y *= csc[c4 + 1];
        v.z *= csc[c4 + 2];
        v.w *= csc[c4 + 3];
        *reinterpret_cast<float4*>(&w[r][c4]) = v;
    }
    __syncthreads();

    #pragma unroll
    for (int st = 0; st < N_STAGES; st++) {
        for (int t = tid; t < ROWS_PB * 64; t += 256) {
            int r = t >> 6, p = t & 63;
            float c = cs_c[st][p], s = cs_s[st][p];
            int i = pi[st][p], j = pj[st][p];
            float xi = w[r][i], xj = w[r][j];
            w[r][i] =  xi * c + xj * s;
            w[r][j] = -xi * s + xj * c;
        }
        __syncthreads();
    }

    for (int t = tid; t < ROWS_PB * GROUP; t += 256) {
        int r = t >> 7, c = t & 127;
        float s = qs[r], rzp = qz[r];
        float q = rintf(w[r][c] / s) + rzp;
        q = fminf(fmaxf(q, 0.0f), QMAXF);
        w[r][c] = (q - rzp) * s;
    }
    __syncthreads();

    #pragma unroll
    for (int st = N_STAGES - 1; st >= 0; st--) {
        for (int t = tid; t < ROWS_PB * 64; t += 256) {
            int r = t >> 6, p = t & 63;
            float c = cs_c[st][p], s = cs_s[st][p];
            int i = pi[st][p], j = pj[st][p];
            float xi = w[r][i], xj = w[r][j];
            w[r][i] = xi * c - xj * s;
            w[r][j] = xi * s + xj * c;
        }
        __syncthreads();
    }

    for (int t = tid; t < ROWS_PB * (GROUP / 2); t += 256) {
        int r  = t >> 6;
        int c2 = (t & 63) * 2;
        float a = w[r][c2]     / csc[c2];
        float b = w[r][c2 + 1] / csc[c2 + 1];
        *reinterpret_cast<__half2*>(
            g_w_h + (size_t)(row0 + r) * IN_F + g * GROUP + c2) =
            __floats2half2_rn(a, b);
    }
}

// ---------------------------------------------------------------------------
// Kernel 2: fp16 mma.sync GEMM with register double-buffered fragments.
// CTA tile 128x256, 8 warps (2x4), warp tile 64x64, BK=64, 4-stage cp.async.
// ---------------------------------------------------------------------------
#define BM 128
#define BN 256
#define BK 64
#define KSTAGES 4
#define A_STAGE_BYTES (BM * BK * 2)
#define B_STAGE_BYTES (BN * BK * 2)
#define STAGE_BYTES   (A_STAGE_BYTES + B_STAGE_BYTES)
#define GEMM_SMEM     (KSTAGES * STAGE_BYTES)            // 196608
#define NKT           (IN_F / BK)                        // 64

__device__ __forceinline__ uint32_t smem_u32(const void* p) {
    uint32_t a;
    asm("{ .reg .u64 t; cvta.to.shared.u64 t, %1; cvt.u32.u64 %0, t; }"
        : "=r"(a) : "l"(p));
    return a;
}
__device__ __forceinline__ void cp_async16(uint32_t saddr, const void* gptr) {
    asm volatile("cp.async.cg.shared.global [%0], [%1], 16;"
                 :: "r"(saddr), "l"(gptr));
}
#define CP_COMMIT() asm volatile("cp.async.commit_group;" ::: "memory")
#define CP_WAIT(n)  asm volatile("cp.async.wait_group %0;" :: "n"(n) : "memory")

__device__ __forceinline__ void ldmatrix_x4(uint32_t* r, uint32_t addr) {
    asm volatile("ldmatrix.sync.aligned.m8n8.x4.shared.b16 {%0,%1,%2,%3}, [%4];"
                 : "=r"(r[0]), "=r"(r[1]), "=r"(r[2]), "=r"(r[3]) : "r"(addr));
}
__device__ __forceinline__ void mma16816(float* c, const uint32_t* a,
                                         const uint32_t* b) {
    asm volatile("mma.sync.aligned.m16n8k16.row.col.f32.f16.f16.f32 "
                 "{%0,%1,%2,%3}, {%4,%5,%6,%7}, {%8,%9}, {%0,%1,%2,%3};"
                 : "+f"(c[0]), "+f"(c[1]), "+f"(c[2]), "+f"(c[3])
                 : "r"(a[0]), "r"(a[1]), "r"(a[2]), "r"(a[3]),
                   "r"(b[0]), "r"(b[1]));
}

__global__ __launch_bounds__(256, 1) void gemm_mma_kernel(
    const float* __restrict__ bias, float* __restrict__ C)
{
    extern __shared__ char smem[];
    const uint32_t sbase = smem_u32(smem);
    const int tid  = threadIdx.x;
    const int wid  = tid >> 5;
    const int lane = tid & 31;
    const int bn = blockIdx.x;
    const int bm = blockIdx.y;
    const int warp_m = wid >> 2;
    const int warp_n = wid & 3;

    const __half* Ag0 = g_x_h + (size_t)(bm * BM) * IN_F;
    const __half* Bg0 = g_w_h + (size_t)(bn * BN) * IN_F;

    float acc[4][8][4];
    #pragma unroll
    for (int i = 0; i < 4; i++)
        #pragma unroll
        for (int j = 0; j < 8; j++)
            #pragma unroll
            for (int k = 0; k < 4; k++) acc[i][j][k] = 0.0f;

    auto load_stage = [&](int kt) {
        const int buf = kt & (KSTAGES - 1);
        const int ko  = kt * BK;
        const __half* Ag = Ag0 + ko;
        const __half* Bg = Bg0 + ko;
        const uint32_t sA = sbase + buf * STAGE_BYTES;
        const uint32_t sB = sA + A_STAGE_BYTES;
        #pragma unroll
        for (int t = 0; t < 4; t++) {
            int v = tid + t * 256;
            int r = v >> 3, c = v & 7;
            uint32_t off = (uint32_t)(r << 7) + (uint32_t)((c ^ (r & 7)) << 4);
            cp_async16(sA + off, Ag + (size_t)r * IN_F + c * 8);
        }
        #pragma unroll
        for (int t = 0; t < 8; t++) {
            int v = tid + t * 256;
            int r = v >> 3, c = v & 7;
            uint32_t off = (uint32_t)(r << 7) + (uint32_t)((c ^ (r & 7)) << 4);
            cp_async16(sB + off, Bg + (size_t)r * IN_F + c * 8);
        }
    };

    const int m_lane  = warp_m * 64 + (lane & 15);
    const int a_half  = lane >> 4;
    const int xa      = m_lane & 7;
    const int n_lane  = warp_n * 64 + (lane & 7) + ((lane >> 4) << 3);
    const int b_half  = (lane >> 3) & 1;
    const int xb      = n_lane & 7;

    #pragma unroll
    for (int s = 0; s < KSTAGES - 1; s++) {
        load_stage(s);
        CP_COMMIT();
    }

    uint32_t a_frag[2][4][4];
    uint32_t b_frag[2][4][4];

    for (int kt = 0; kt < NKT; kt++) {
        CP_WAIT(KSTAGES - 2);
        __syncthreads();

        if (kt + KSTAGES - 1 < NKT) load_stage(kt + KSTAGES - 1);
        CP_COMMIT();

        const int buf = kt & (KSTAGES - 1);
        const uint32_t sA = sbase + buf * STAGE_BYTES;
        const uint32_t sB = sA + A_STAGE_BYTES;
        const uint32_t aRow = sA + (uint32_t)(m_lane << 7);
        const uint32_t bRow = sB + (uint32_t)(n_lane << 7);

        // prime kk=0 fragments into buffer 0
        {
            const uint32_t ac = (uint32_t)(((0 + a_half) ^ xa) << 4);
            const uint32_t bc = (uint32_t)(((0 + b_half) ^ xb) << 4);
            #pragma unroll
            for (int mt = 0; mt < 4; mt++)
                ldmatrix_x4(a_frag[0][mt], aRow + (uint32_t)(mt << 11) + ac);
            #pragma unroll
            for (int nt = 0; nt < 4; nt++)
                ldmatrix_x4(b_frag[0][nt], bRow + (uint32_t)(nt << 11) + bc);
        }

        #pragma unroll
        for (int kk = 0; kk < 4; kk++) {
            const int cur = kk & 1;
            if (kk < 3) {
                const int nxt = cur ^ 1;
                const uint32_t ac =
                    (uint32_t)((((kk + 1) * 2 + a_half) ^ xa) << 4);
                const uint32_t bc =
                    (uint32_t)((((kk + 1) * 2 + b_half) ^ xb) << 4);
                #pragma unroll
                for (int mt = 0; mt < 4; mt++)
                    ldmatrix_x4(a_frag[nxt][mt],
                                aRow + (uint32_t)(mt << 11) + ac);
                #pragma unroll
                for (int nt = 0; nt < 4; nt++)
                    ldmatrix_x4(b_frag[nxt][nt],
                                bRow + (uint32_t)(nt << 11) + bc);
            }
            #pragma unroll
            for (int mt = 0; mt < 4; mt++) {
                #pragma unroll
                for (int nt = 0; nt < 4; nt++) {
                    mma16816(acc[mt][2 * nt],     a_frag[cur][mt],
                             &b_frag[cur][nt][0]);
                    mma16816(acc[mt][2 * nt + 1], a_frag[cur][mt],
                             &b_frag[cur][nt][2]);
                }
            }
        }
    }

    const int row_base = bm * BM + warp_m * 64 + (lane >> 2);
    const int col_base = bn * BN + warp_n * 64 + 2 * (lane & 3);
    #pragma unroll
    for (int mt = 0; mt < 4; mt++) {
        const int r0 = row_base + mt * 16;
        #pragma unroll
        for (int n8 = 0; n8 < 8; n8++) {
            const int col = col_base + n8 * 8;
            float2 bv = *reinterpret_cast<const float2*>(bias + col);
            float2 o0, o1;
            o0.x = acc[mt][n8][0] + bv.x;
            o0.y = acc[mt][n8][1] + bv.y;
            o1.x = acc[mt][n8][2] + bv.x;
            o1.y = acc[mt][n8][3] + bv.y;
            *reinterpret_cast<float2*>(C + (size_t)r0 * OUT_F + col)       = o0;
            *reinterpret_cast<float2*>(C + (size_t)(r0 + 8) * OUT_F + col) = o1;
        }
    }
}

// ---------------------------------------------------------------------------
// Launch
// ---------------------------------------------------------------------------
extern "C" void kernel_launch(void* const* d_in, const int* in_sizes, int n_in,
                              void* d_out, int out_size)
{
    const float* x              = (const float*)d_in[0];
    const float* weight         = (const float*)d_in[1];
    const float* bias           = (const float*)d_in[2];
    const float* channel_scales = (const float*)d_in[3];
    const float* theta          = (const float*)d_in[4];
    const float* q_scale        = (const float*)d_in[5];
    const float* q_zp           = (const float*)d_in[6];
    const int*   pairs          = (const int*)d_in[7];
    float* out = (float*)d_out;

    cudaFuncSetAttribute(gemm_mma_kernel,
                         cudaFuncAttributeMaxDynamicSharedMemorySize, GEMM_SMEM);

    convert_x_kernel<<<(size_t)N_TOK * IN_F / 8 / 256, 256>>>(x);

    dim3 tgrid(NGROUPS, OUT_F / ROWS_PB);
    transform_kernel<<<tgrid, 256>>>(weight, channel_scales, theta,
                                     q_scale, q_zp, pairs);

    dim3 grid(OUT_F / BN, N_TOK / BM);
    gemm_mma_kernel<<<grid, 256, GEMM_SMEM>>>(bias, out);
}

// round 7
// speedup vs baseline: 8.3951x; 1.0042x over previous
#include <cuda_runtime.h>
#include <cuda_fp16.h>
#include <cstdint>

#define IN_F     4096
#define OUT_F    4096
#define N_TOK    8192
#define GROUP    128
#define NGROUPS  (IN_F / GROUP)
#define N_STAGES 4
#define QMAXF    15.0f

// ---------------- scratch (device globals; no runtime allocation) ----------
__device__ __half g_w_h[(size_t)OUT_F * IN_F];
__device__ __half g_x_h[(size_t)N_TOK * IN_F];

// ---------------------------------------------------------------------------
// Kernel 0: x -> fp16 (8 elems/thread, 16B stores)
// ---------------------------------------------------------------------------
__global__ __launch_bounds__(256) void convert_x_kernel(const float* __restrict__ x)
{
    size_t i = ((size_t)blockIdx.x * 256 + threadIdx.x) * 8;
    float4 v0 = *reinterpret_cast<const float4*>(x + i);
    float4 v1 = *reinterpret_cast<const float4*>(x + i + 4);
    __half2 h[4];
    h[0] = __floats2half2_rn(v0.x, v0.y);
    h[1] = __floats2half2_rn(v0.z, v0.w);
    h[2] = __floats2half2_rn(v1.x, v1.y);
    h[3] = __floats2half2_rn(v1.z, v1.w);
    *reinterpret_cast<uint4*>(g_x_h + i) = *reinterpret_cast<const uint4*>(h);
}

// ---------------------------------------------------------------------------
// Kernel 1: weight transform (unchanged from R6 — correct & fast enough)
// ---------------------------------------------------------------------------
#define ROWS_PB 64
#define WPAD    132

__global__ __launch_bounds__(256) void transform_kernel(
    const float* __restrict__ weight,
    const float* __restrict__ channel_scales,
    const float* __restrict__ theta,
    const float* __restrict__ q_scale,
    const float* __restrict__ q_zp,
    const int*   __restrict__ pairs)
{
    const int g    = blockIdx.x;
    const int row0 = blockIdx.y * ROWS_PB;
    const int tid  = threadIdx.x;

    __shared__ float w[ROWS_PB][WPAD];
    __shared__ float cs_c[N_STAGES][64], cs_s[N_STAGES][64];
    __shared__ int   pi[N_STAGES][64], pj[N_STAGES][64];
    __shared__ float csc[GROUP];
    __shared__ float qs[ROWS_PB], qz[ROWS_PB];

    if (tid < GROUP) csc[tid] = channel_scales[g * GROUP + tid];
    {
        int st = tid >> 6, p = tid & 63;
        float s, c;
        sincosf(theta[st * (IN_F / 2) + g * 64 + p], &s, &c);
        cs_c[st][p] = c;
        cs_s[st][p] = s;
        pi[st][p] = pairs[st * IN_F + g * GROUP + 2 * p];
        pj[st][p] = pairs[st * IN_F + g * GROUP + 2 * p + 1];
    }
    if (tid < ROWS_PB) {
        int gi = (row0 + tid) * NGROUPS + g;
        qs[tid] = fminf(fmaxf(q_scale[gi], 1e-5f), 1e5f);
        qz[tid] = fminf(fmaxf(-rintf(q_zp[gi]), 0.0f), QMAXF);
    }
    __syncthreads();

    for (int idx = tid; idx < ROWS_PB * (GROUP / 4); idx += 256) {
        int r  = idx >> 5;
        int c4 = (idx & 31) * 4;
        float4 v = *reinterpret_cast<const float4*>(
            weight + (size_t)(row0 + r) * IN_F + g * GROUP + c4);
        v.x *= csc[c4];
        v.y *= csc[c4 + 1];
        v.z *= csc[c4 + 2];
        v.w *= csc[c4 + 3];
        *reinterpret_cast<float4*>(&w[r][c4]) = v;
    }
    __syncthreads();

    #pragma unroll
    for (int st = 0; st < N_STAGES; st++) {
        for (int t = tid; t < ROWS_PB * 64; t += 256) {
            int r = t >> 6, p = t & 63;
            float c = cs_c[st][p], s = cs_s[st][p];
            int i = pi[st][p], j = pj[st][p];
            float xi = w[r][i], xj = w[r][j];
            w[r][i] =  xi * c + xj * s;
            w[r][j] = -xi * s + xj * c;
        }
        __syncthreads();
    }

    for (int t = tid; t < ROWS_PB * GROUP; t += 256) {
        int r = t >> 7, c = t & 127;
        float s = qs[r], rzp = qz[r];
        float q = rintf(w[r][c] / s) + rzp;
        q = fminf(fmaxf(q, 0.0f), QMAXF);
        w[r][c] = (q - rzp) * s;
    }
    __syncthreads();

    #pragma unroll
    for (int st = N_STAGES - 1; st >= 0; st--) {
        for (int t = tid; t < ROWS_PB * 64; t += 256) {
            int r = t >> 6, p = t & 63;
            float c = cs_c[st][p], s = cs_s[st][p];
            int i = pi[st][p], j = pj[st][p];
            float xi = w[r][i], xj = w[r][j];
            w[r][i] = xi * c - xj * s;
            w[r][j] = xi * s + xj * c;
        }
        __syncthreads();
    }

    for (int t = tid; t < ROWS_PB * (GROUP / 2); t += 256) {
        int r  = t >> 6;
        int c2 = (t & 63) * 2;
        float a = w[r][c2]     / csc[c2];
        float b = w[r][c2 + 1] / csc[c2 + 1];
        *reinterpret_cast<__half2*>(
            g_w_h + (size_t)(row0 + r) * IN_F + g * GROUP + c2) =
            __floats2half2_rn(a, b);
    }
}

// ---------------------------------------------------------------------------
// Kernel 2: fp16 mma.sync GEMM. CTA 128x256, 512 threads, 16 warps (2x8),
// warp tile 64x32 (low reg pressure -> 4 warps/SMSP), BK=64, 4-stage cp.async.
// ---------------------------------------------------------------------------
#define BM 128
#define BN 256
#define BK 64
#define KSTAGES 4
#define NTHREADS 512
#define A_STAGE_BYTES (BM * BK * 2)
#define B_STAGE_BYTES (BN * BK * 2)
#define STAGE_BYTES   (A_STAGE_BYTES + B_STAGE_BYTES)
#define GEMM_SMEM     (KSTAGES * STAGE_BYTES)            // 196608
#define NKT           (IN_F / BK)                        // 64

__device__ __forceinline__ uint32_t smem_u32(const void* p) {
    uint32_t a;
    asm("{ .reg .u64 t; cvta.to.shared.u64 t, %1; cvt.u32.u64 %0, t; }"
        : "=r"(a) : "l"(p));
    return a;
}
__device__ __forceinline__ void cp_async16(uint32_t saddr, const void* gptr) {
    asm volatile("cp.async.cg.shared.global [%0], [%1], 16;"
                 :: "r"(saddr), "l"(gptr));
}
#define CP_COMMIT() asm volatile("cp.async.commit_group;" ::: "memory")
#define CP_WAIT(n)  asm volatile("cp.async.wait_group %0;" :: "n"(n) : "memory")

__device__ __forceinline__ void ldmatrix_x4(uint32_t* r, uint32_t addr) {
    asm volatile("ldmatrix.sync.aligned.m8n8.x4.shared.b16 {%0,%1,%2,%3}, [%4];"
                 : "=r"(r[0]), "=r"(r[1]), "=r"(r[2]), "=r"(r[3]) : "r"(addr));
}
__device__ __forceinline__ void mma16816(float* c, const uint32_t* a,
                                         const uint32_t* b) {
    asm volatile("mma.sync.aligned.m16n8k16.row.col.f32.f16.f16.f32 "
                 "{%0,%1,%2,%3}, {%4,%5,%6,%7}, {%8,%9}, {%0,%1,%2,%3};"
                 : "+f"(c[0]), "+f"(c[1]), "+f"(c[2]), "+f"(c[3])
                 : "r"(a[0]), "r"(a[1]), "r"(a[2]), "r"(a[3]),
                   "r"(b[0]), "r"(b[1]));
}

__global__ __launch_bounds__(NTHREADS, 1) void gemm_mma_kernel(
    const float* __restrict__ bias, float* __restrict__ C)
{
    extern __shared__ char smem[];
    const uint32_t sbase = smem_u32(smem);
    const int tid  = threadIdx.x;
    const int wid  = tid >> 5;
    const int lane = tid & 31;
    const int bn = blockIdx.x;
    const int bm = blockIdx.y;
    const int warp_m = wid >> 3;         // 0..1  -> 64 rows each
    const int warp_n = wid & 7;          // 0..7  -> 32 cols each

    const __half* Ag0 = g_x_h + (size_t)(bm * BM) * IN_F;
    const __half* Bg0 = g_w_h + (size_t)(bn * BN) * IN_F;

    float acc[4][4][4];                  // mt x n8 x 4
    #pragma unroll
    for (int i = 0; i < 4; i++)
        #pragma unroll
        for (int j = 0; j < 4; j++)
            #pragma unroll
            for (int k = 0; k < 4; k++) acc[i][j][k] = 0.0f;

    auto load_stage = [&](int kt) {
        const int buf = kt & (KSTAGES - 1);
        const int ko  = kt * BK;
        const __half* Ag = Ag0 + ko;
        const __half* Bg = Bg0 + ko;
        const uint32_t sA = sbase + buf * STAGE_BYTES;
        const uint32_t sB = sA + A_STAGE_BYTES;
        #pragma unroll
        for (int t = 0; t < 2; t++) {    // A: 1024 chunks / 512 thr
            int v = tid + t * NTHREADS;
            int r = v >> 3, c = v & 7;
            uint32_t off = (uint32_t)(r << 7) + (uint32_t)((c ^ (r & 7)) << 4);
            cp_async16(sA + off, Ag + (size_t)r * IN_F + c * 8);
        }
        #pragma unroll
        for (int t = 0; t < 4; t++) {    // B: 2048 chunks / 512 thr
            int v = tid + t * NTHREADS;
            int r = v >> 3, c = v & 7;
            uint32_t off = (uint32_t)(r << 7) + (uint32_t)((c ^ (r & 7)) << 4);
            cp_async16(sB + off, Bg + (size_t)r * IN_F + c * 8);
        }
    };

    const int m_lane  = warp_m * 64 + (lane & 15);
    const int a_half  = lane >> 4;
    const int xa      = m_lane & 7;
    const int n_lane  = warp_n * 32 + (lane & 7) + ((lane >> 4) << 3);
    const int b_half  = (lane >> 3) & 1;
    const int xb      = n_lane & 7;

    #pragma unroll
    for (int s = 0; s < KSTAGES - 1; s++) {
        load_stage(s);
        CP_COMMIT();
    }

    for (int kt = 0; kt < NKT; kt++) {
        CP_WAIT(KSTAGES - 2);
        __syncthreads();

        if (kt + KSTAGES - 1 < NKT) load_stage(kt + KSTAGES - 1);
        CP_COMMIT();

        const int buf = kt & (KSTAGES - 1);
        const uint32_t sA = sbase + buf * STAGE_BYTES;
        const uint32_t sB = sA + A_STAGE_BYTES;
        const uint32_t aRow = sA + (uint32_t)(m_lane << 7);
        const uint32_t bRow = sB + (uint32_t)(n_lane << 7);

        #pragma unroll
        for (int kk = 0; kk < 4; kk++) {
            uint32_t a_frag[4][4];
            uint32_t b_frag[2][4];
            const uint32_t ac = (uint32_t)(((kk * 2 + a_half) ^ xa) << 4);
            const uint32_t bc = (uint32_t)(((kk * 2 + b_half) ^ xb) << 4);
            #pragma unroll
            for (int mt = 0; mt < 4; mt++)
                ldmatrix_x4(a_frag[mt], aRow + (uint32_t)(mt << 11) + ac);
            #pragma unroll
            for (int nt = 0; nt < 2; nt++)
                ldmatrix_x4(b_frag[nt], bRow + (uint32_t)(nt << 11) + bc);
            #pragma unroll
            for (int mt = 0; mt < 4; mt++) {
                #pragma unroll
                for (int nt = 0; nt < 2; nt++) {
                    mma16816(acc[mt][2 * nt],     a_frag[mt], &b_frag[nt][0]);
                    mma16816(acc[mt][2 * nt + 1], a_frag[mt], &b_frag[nt][2]);
                }
            }
        }
    }

    const int row_base = bm * BM + warp_m * 64 + (lane >> 2);
    const int col_base = bn * BN + warp_n * 32 + 2 * (lane & 3);
    #pragma unroll
    for (int mt = 0; mt < 4; mt++) {
        const int r0 = row_base + mt * 16;
        #pragma unroll
        for (int n8 = 0; n8 < 4; n8++) {
            const int col = col_base + n8 * 8;
            float2 bv = *reinterpret_cast<const float2*>(bias + col);
            float2 o0, o1;
            o0.x = acc[mt][n8][0] + bv.x;
            o0.y = acc[mt][n8][1] + bv.y;
            o1.x = acc[mt][n8][2] + bv.x;
            o1.y = acc[mt][n8][3] + bv.y;
            *reinterpret_cast<float2*>(C + (size_t)r0 * OUT_F + col)       = o0;
            *reinterpret_cast<float2*>(C + (size_t)(r0 + 8) * OUT_F + col) = o1;
        }
    }
}

// ---------------------------------------------------------------------------
// Launch
// ---------------------------------------------------------------------------
extern "C" void kernel_launch(void* const* d_in, const int* in_sizes, int n_in,
                              void* d_out, int out_size)
{
    const float* x              = (const float*)d_in[0];
    const float* weight         = (const float*)d_in[1];
    const float* bias           = (const float*)d_in[2];
    const float* channel_scales = (const float*)d_in[3];
    const float* theta          = (const float*)d_in[4];
    const float* q_scale        = (const float*)d_in[5];
    const float* q_zp           = (const float*)d_in[6];
    const int*   pairs          = (const int*)d_in[7];
    float* out = (float*)d_out;

    cudaFuncSetAttribute(gemm_mma_kernel,
                         cudaFuncAttributeMaxDynamicSharedMemorySize, GEMM_SMEM);

    convert_x_kernel<<<(size_t)N_TOK * IN_F / 8 / 256, 256>>>(x);

    dim3 tgrid(NGROUPS, OUT_F / ROWS_PB);
    transform_kernel<<<tgrid, 256>>>(weight, channel_scales, theta,
                                     q_scale, q_zp, pairs);

    dim3 grid(OUT_F / BN, N_TOK / BM);
    gemm_mma_kernel<<<grid, NTHREADS, GEMM_SMEM>>>(bias, out);
}